// round 3
// baseline (speedup 1.0000x reference)
#include <cuda_runtime.h>

#define NN   50000
#define EE   800000
#define ETOT 850000   // E + N self loops
#define FIN  128
#define F1   128      // HEADS*HID
#define H    4
#define HID  32
#define FOUT 32

// ---------------- scratch (device globals; no allocations allowed) ----------
__device__ __align__(16) float g_h1[NN * F1];      // layer1 transformed features
__device__ __align__(16) float g_out1[NN * F1];    // layer1 aggregate -> elu output
__device__ __align__(16) float g_als1[NN * H];
__device__ __align__(16) float g_ald1[NN * H];
__device__ __align__(16) float g_m1[NN * H];
__device__ __align__(16) float g_d1[NN * H];
__device__ __align__(16) float g_e1[(size_t)ETOT * H];   // logits, then p
__device__ __align__(16) float g_h2[NN * FOUT];
__device__ __align__(16) float g_als2[NN];
__device__ __align__(16) float g_ald2[NN];
__device__ __align__(16) float g_m2[NN];
__device__ __align__(16) float g_d2[NN];
__device__ __align__(16) float g_e2[ETOT];
__device__ int g_src[ETOT];
__device__ int g_dst[ETOT];
__device__ int g_is64;

// ---------------- helpers ---------------------------------------------------
__device__ __forceinline__ void atomicMaxF(float* a, float v) {
    if (v >= 0.f) atomicMax((int*)a, __float_as_int(v));
    else          atomicMin((unsigned int*)a, __float_as_uint(v));
}

__device__ __forceinline__ void red_add_v4(float* p, float4 v) {
    asm volatile("red.global.add.v4.f32 [%0], {%1,%2,%3,%4};"
                 :: "l"(p), "f"(v.x), "f"(v.y), "f"(v.z), "f"(v.w) : "memory");
}

__device__ __forceinline__ float lrelu(float v) { return v > 0.f ? v : 0.2f * v; }

// ---------------- edge dtype detection + decode ------------------------------
// If edge_index is int64, its int32 view has zero high words at odd positions
// (all node ids < 50000 => high word 0). If int32, odd positions are random
// src ids; P[256 random ids all zero] ~ (1/50000)^256 ~ 0.
__global__ void k_detect(const int* __restrict__ ei32) {
    __shared__ int any_nonzero;
    if (threadIdx.x == 0) any_nonzero = 0;
    __syncthreads();
    // stride the samples across the first half of the buffer
    if (ei32[2 * (threadIdx.x * 1237) + 1] != 0) atomicOr(&any_nonzero, 1);
    __syncthreads();
    if (threadIdx.x == 0) g_is64 = any_nonzero ? 0 : 1;
}

__global__ void k_decode(const void* __restrict__ ei) {
    int i = blockIdx.x * blockDim.x + threadIdx.x;
    if (i >= ETOT) return;
    int s, d;
    if (i >= EE) {
        s = d = i - EE;                     // self loop
    } else if (g_is64) {
        const long long* p = (const long long*)ei;
        s = (int)p[i]; d = (int)p[EE + i];
    } else {
        const int* q = (const int*)ei;
        s = q[i]; d = q[EE + i];
    }
    if ((unsigned)s >= NN) s = 0;
    if ((unsigned)d >= NN) d = 0;
    g_src[i] = s;
    g_dst[i] = d;
}

// ---------------- init: biases + softmax state + output ---------------------
__global__ void k_init(float* __restrict__ out,
                       const float* __restrict__ b1,
                       const float* __restrict__ b2) {
    int i = blockIdx.x * blockDim.x + threadIdx.x;
    if (i < NN * F1)   g_out1[i] = b1[i & 127];
    if (i < NN * FOUT) out[i]    = b2[i & 31];
    if (i < NN * H) { g_m1[i] = __int_as_float(0xff800000); g_d1[i] = 0.f; }
    if (i < NN)     { g_m2[i] = __int_as_float(0xff800000); g_d2[i] = 0.f; }
}

// ---------------- GEMM1: h1 = x @ W1  (50000x128 @ 128x128) ------------------
__global__ void k_gemm1(const float* __restrict__ x, const float* __restrict__ W) {
    __shared__ float Ws[64 * 128];   // [kk][c]
    __shared__ float Xs[64 * 64];    // [m][kk]
    int tid = threadIdx.x;
    int tx = tid & 31;               // col group: c0 = tx*4
    int ty = tid >> 5;               // node group: m0 = ty*8
    int bm = blockIdx.x * 64;

    float acc[8][4];
#pragma unroll
    for (int i = 0; i < 8; i++)
#pragma unroll
        for (int j = 0; j < 4; j++) acc[i][j] = 0.f;

    for (int kt = 0; kt < 2; kt++) {
        const float4* Wg = (const float4*)(W + kt * 64 * 128);
        float4* Ws4 = (float4*)Ws;
#pragma unroll
        for (int r = 0; r < 8; r++) Ws4[tid + r * 256] = Wg[tid + r * 256];
        float4* Xs4 = (float4*)Xs;
#pragma unroll
        for (int r = 0; r < 4; r++) {
            int v = tid + r * 256;        // float4 index, 16 per row
            int m = v >> 4, kv = v & 15;
            int node = bm + m;
            float4 val = make_float4(0.f, 0.f, 0.f, 0.f);
            if (node < NN)
                val = *(const float4*)(x + node * 128 + kt * 64 + kv * 4);
            Xs4[v] = val;
        }
        __syncthreads();
#pragma unroll 8
        for (int kk = 0; kk < 64; kk++) {
            float4 w = ((const float4*)Ws)[kk * 32 + tx];
#pragma unroll
            for (int i = 0; i < 8; i++) {
                float xv = Xs[(ty * 8 + i) * 64 + kk];
                acc[i][0] += xv * w.x;
                acc[i][1] += xv * w.y;
                acc[i][2] += xv * w.z;
                acc[i][3] += xv * w.w;
            }
        }
        __syncthreads();
    }
#pragma unroll
    for (int i = 0; i < 8; i++) {
        int node = bm + ty * 8 + i;
        if (node < NN)
            *(float4*)(g_h1 + node * 128 + tx * 4) =
                make_float4(acc[i][0], acc[i][1], acc[i][2], acc[i][3]);
    }
}

// ---------------- attention scalars layer1 ----------------------------------
__global__ void k_al1(const float* __restrict__ a_src, const float* __restrict__ a_dst) {
    int i = blockIdx.x * blockDim.x + threadIdx.x;
    if (i >= NN * H) return;
    int n = i >> 2, h = i & 3;
    const float* hp = g_h1 + n * 128 + h * 32;
    float s = 0.f, d = 0.f;
#pragma unroll
    for (int j = 0; j < 8; j++) {
        float4 v  = *(const float4*)(hp + j * 4);
        float4 as = *(const float4*)(a_src + h * 32 + j * 4);
        float4 ad = *(const float4*)(a_dst + h * 32 + j * 4);
        s += v.x * as.x + v.y * as.y + v.z * as.z + v.w * as.w;
        d += v.x * ad.x + v.y * ad.y + v.z * ad.z + v.w * ad.w;
    }
    g_als1[i] = s;
    g_ald1[i] = d;
}

// ---------------- layer1 edge pass A: logits + segment max -------------------
__global__ void k_max1() {
    int i = blockIdx.x * blockDim.x + threadIdx.x;
    if (i >= ETOT) return;
    int s = g_src[i], d = g_dst[i];
    float4 as = *(const float4*)(g_als1 + s * 4);
    float4 ad = *(const float4*)(g_ald1 + d * 4);
    float4 e;
    e.x = lrelu(as.x + ad.x);
    e.y = lrelu(as.y + ad.y);
    e.z = lrelu(as.z + ad.z);
    e.w = lrelu(as.w + ad.w);
    *(float4*)(g_e1 + (size_t)i * 4) = e;
    atomicMaxF(&g_m1[d * 4 + 0], e.x);
    atomicMaxF(&g_m1[d * 4 + 1], e.y);
    atomicMaxF(&g_m1[d * 4 + 2], e.z);
    atomicMaxF(&g_m1[d * 4 + 3], e.w);
}

// ---------------- layer1 edge pass B: exp + denom ----------------------------
__global__ void k_exp1() {
    int i = blockIdx.x * blockDim.x + threadIdx.x;
    if (i >= ETOT) return;
    int d = g_dst[i];
    float4 e = *(const float4*)(g_e1 + (size_t)i * 4);
    float4 m = *(const float4*)(g_m1 + d * 4);
    float4 p;
    p.x = __expf(e.x - m.x);
    p.y = __expf(e.y - m.y);
    p.z = __expf(e.z - m.z);
    p.w = __expf(e.w - m.w);
    *(float4*)(g_e1 + (size_t)i * 4) = p;
    red_add_v4(&g_d1[d * 4], p);
}

// ---------------- layer1 edge pass C: aggregate (warp per edge) --------------
__global__ void k_agg1() {
    int gid = blockIdx.x * blockDim.x + threadIdx.x;
    int w = gid >> 5, lane = gid & 31;
    if (w >= ETOT) return;
    int s = g_src[w], d = g_dst[w];
    int head = lane >> 3;
    float alpha = g_e1[(size_t)w * 4 + head] / fmaxf(g_d1[d * 4 + head], 1e-16f);
    float4 v = *(const float4*)(g_h1 + s * 128 + lane * 4);
    v.x *= alpha; v.y *= alpha; v.z *= alpha; v.w *= alpha;
    red_add_v4(g_out1 + d * 128 + lane * 4, v);
}

// ---------------- elu(out1 + b1) in place ------------------------------------
__global__ void k_elu() {
    int i = blockIdx.x * blockDim.x + threadIdx.x;
    if (i >= NN * F1) return;
    float v = g_out1[i];   // bias already added at init
    g_out1[i] = v > 0.f ? v : __expf(v) - 1.f;
}

// ---------------- GEMM2: h2 = elu_out @ W2  (50000x128 @ 128x32) -------------
__global__ void k_gemm2(const float* __restrict__ W) {
    __shared__ float Ws[128 * 32];   // [k][c]
    __shared__ float Xs[64 * 128];   // [m][k]
    int tid = threadIdx.x;
    int tx = tid & 31;               // col
    int ty = tid >> 5;               // node group of 8
    int bm = blockIdx.x * 64;

    float4* Ws4 = (float4*)Ws;
    const float4* Wg = (const float4*)W;
#pragma unroll
    for (int r = 0; r < 4; r++) Ws4[tid + r * 256] = Wg[tid + r * 256];

    float4* Xs4 = (float4*)Xs;
#pragma unroll
    for (int r = 0; r < 8; r++) {
        int v = tid + r * 256;       // float4 index; 32 per row
        int m = v >> 5, kv = v & 31;
        int node = bm + m;
        float4 val = make_float4(0.f, 0.f, 0.f, 0.f);
        if (node < NN) val = *(const float4*)(g_out1 + node * 128 + kv * 4);
        Xs4[v] = val;
    }
    __syncthreads();

    float acc[8];
#pragma unroll
    for (int i = 0; i < 8; i++) acc[i] = 0.f;
#pragma unroll 8
    for (int k = 0; k < 128; k++) {
        float w = Ws[k * 32 + tx];
#pragma unroll
        for (int i = 0; i < 8; i++) acc[i] += Xs[(ty * 8 + i) * 128 + k] * w;
    }
#pragma unroll
    for (int i = 0; i < 8; i++) {
        int node = bm + ty * 8 + i;
        if (node < NN) g_h2[node * 32 + tx] = acc[i];
    }
}

// ---------------- attention scalars layer2 ----------------------------------
__global__ void k_al2(const float* __restrict__ a_src, const float* __restrict__ a_dst) {
    int n = blockIdx.x * blockDim.x + threadIdx.x;
    if (n >= NN) return;
    const float* hp = g_h2 + n * 32;
    float s = 0.f, d = 0.f;
#pragma unroll
    for (int j = 0; j < 8; j++) {
        float4 v  = *(const float4*)(hp + j * 4);
        float4 as = *(const float4*)(a_src + j * 4);
        float4 ad = *(const float4*)(a_dst + j * 4);
        s += v.x * as.x + v.y * as.y + v.z * as.z + v.w * as.w;
        d += v.x * ad.x + v.y * ad.y + v.z * ad.z + v.w * ad.w;
    }
    g_als2[n] = s;
    g_ald2[n] = d;
}

// ---------------- layer2 edge passes -----------------------------------------
__global__ void k_max2() {
    int i = blockIdx.x * blockDim.x + threadIdx.x;
    if (i >= ETOT) return;
    int s = g_src[i], d = g_dst[i];
    float e = lrelu(g_als2[s] + g_ald2[d]);
    g_e2[i] = e;
    atomicMaxF(&g_m2[d], e);
}

__global__ void k_exp2() {
    int i = blockIdx.x * blockDim.x + threadIdx.x;
    if (i >= ETOT) return;
    int d = g_dst[i];
    float p = __expf(g_e2[i] - g_m2[d]);
    g_e2[i] = p;
    atomicAdd(&g_d2[d], p);
}

// 8 threads per edge, each handles 4 channels
__global__ void k_agg2(float* __restrict__ out) {
    int gid = blockIdx.x * blockDim.x + threadIdx.x;
    int e = gid >> 3, j = gid & 7;
    if (e >= ETOT) return;
    int s = g_src[e], d = g_dst[e];
    float alpha = g_e2[e] / fmaxf(g_d2[d], 1e-16f);
    float4 v = *(const float4*)(g_h2 + s * 32 + j * 4);
    v.x *= alpha; v.y *= alpha; v.z *= alpha; v.w *= alpha;
    red_add_v4(out + d * 32 + j * 4, v);
}

// ---------------- launcher ---------------------------------------------------
extern "C" void kernel_launch(void* const* d_in, const int* in_sizes, int n_in,
                              void* d_out, int out_size) {
    const float* x      = (const float*)d_in[0];
    const float* W1     = (const float*)d_in[1];
    const float* a_src1 = (const float*)d_in[2];
    const float* a_dst1 = (const float*)d_in[3];
    const float* b1     = (const float*)d_in[4];
    const float* W2     = (const float*)d_in[5];
    const float* a_src2 = (const float*)d_in[6];
    const float* a_dst2 = (const float*)d_in[7];
    const float* b2     = (const float*)d_in[8];
    const void*  ei     = (const void*)d_in[9];
    float* out = (float*)d_out;

    k_detect<<<1, 256>>>((const int*)ei);
    k_decode<<<(ETOT + 255) / 256, 256>>>(ei);
    k_init  <<<(NN * F1 + 255) / 256, 256>>>(out, b1, b2);
    k_gemm1 <<<(NN + 63) / 64,        256>>>(x, W1);
    k_al1   <<<(NN * H + 255) / 256,  256>>>(a_src1, a_dst1);
    k_max1  <<<(ETOT + 255) / 256,    256>>>();
    k_exp1  <<<(ETOT + 255) / 256,    256>>>();
    k_agg1  <<<(ETOT * 32 + 255) / 256, 256>>>();
    k_elu   <<<(NN * F1 + 255) / 256, 256>>>();
    k_gemm2 <<<(NN + 63) / 64,        256>>>(W2);
    k_al2   <<<(NN + 255) / 256,      256>>>(a_src2, a_dst2);
    k_max2  <<<(ETOT + 255) / 256,    256>>>();
    k_exp2  <<<(ETOT + 255) / 256,    256>>>();
    k_agg2  <<<(ETOT * 8 + 255) / 256, 256>>>(out);
}

// round 4
// speedup vs baseline: 1.1888x; 1.1888x over previous
#include <cuda_runtime.h>

#define NN   50000
#define EE   800000
#define ETOT 850000   // E + N self loops
#define F1   128      // HEADS*HID
#define H    4
#define FOUT 32

// ---------------- scratch (device globals; no allocations allowed) ----------
__device__ __align__(16) float g_h1[NN * F1];      // layer1 transformed features
__device__ __align__(16) float g_out1[NN * F1];    // layer1 aggregate (pre-ELU)
__device__ __align__(16) float g_als1[NN * H];
__device__ __align__(16) float g_ald1[NN * H];
__device__ __align__(16) float g_d1[NN * H];       // denom -> 1/denom
__device__ __align__(16) float g_e1[(size_t)ETOT * H];   // p = exp(logit)
__device__ __align__(16) float g_h2[NN * FOUT];
__device__ __align__(16) float g_als2[NN];
__device__ __align__(16) float g_ald2[NN];
__device__ __align__(16) float g_d2[NN];           // denom -> 1/denom
__device__ __align__(16) float g_e2[ETOT];
__device__ int g_src[ETOT];
__device__ int g_dst[ETOT];
__device__ int g_is64;

// ---------------- helpers ---------------------------------------------------
__device__ __forceinline__ void red_add_v4(float* p, float4 v) {
    asm volatile("red.global.add.v4.f32 [%0], {%1,%2,%3,%4};"
                 :: "l"(p), "f"(v.x), "f"(v.y), "f"(v.z), "f"(v.w) : "memory");
}

__device__ __forceinline__ float lrelu(float v) { return v > 0.f ? v : 0.2f * v; }

// ---------------- edge dtype detection + decode ------------------------------
__global__ void k_detect(const int* __restrict__ ei32) {
    __shared__ int any_nonzero;
    if (threadIdx.x == 0) any_nonzero = 0;
    __syncthreads();
    if (ei32[2 * (threadIdx.x * 1237) + 1] != 0) atomicOr(&any_nonzero, 1);
    __syncthreads();
    if (threadIdx.x == 0) g_is64 = any_nonzero ? 0 : 1;
}

__global__ void k_decode(const void* __restrict__ ei) {
    int i = blockIdx.x * blockDim.x + threadIdx.x;
    if (i >= ETOT) return;
    int s, d;
    if (i >= EE) {
        s = d = i - EE;                     // self loop
    } else if (g_is64) {
        const long long* p = (const long long*)ei;
        s = (int)p[i]; d = (int)p[EE + i];
    } else {
        const int* q = (const int*)ei;
        s = q[i]; d = q[EE + i];
    }
    if ((unsigned)s >= NN) s = 0;
    if ((unsigned)d >= NN) d = 0;
    g_src[i] = s;
    g_dst[i] = d;
}

// ---------------- init: biases + denom zeros + output -----------------------
__global__ void k_init(float* __restrict__ out,
                       const float* __restrict__ b1,
                       const float* __restrict__ b2) {
    int i = blockIdx.x * blockDim.x + threadIdx.x;
    if (i < NN * F1)   g_out1[i] = b1[i & 127];
    if (i < NN * FOUT) out[i]    = b2[i & 31];
    if (i < NN * H)    g_d1[i] = 0.f;
    if (i < NN)        g_d2[i] = 0.f;
}

// ---------------- GEMM1: h1 = x @ W1  (50000x128 @ 128x128) ------------------
// 256 thr/blk, 128-node tile, 8x8 per-thread micro-tile, K tiled by 16.
__global__ __launch_bounds__(256) void k_gemm1(const float* __restrict__ x,
                                               const float* __restrict__ W) {
    __shared__ float Xs[16 * 128];   // [kk][m] (transposed)
    __shared__ float Ws[16 * 128];   // [kk][c]
    int tid = threadIdx.x;
    int tx = tid & 15;               // col group: c0 = tx*8
    int ty = tid >> 4;               // node group: m0 = ty*8
    int bm = blockIdx.x * 128;

    float acc[8][8];
#pragma unroll
    for (int i = 0; i < 8; i++)
#pragma unroll
        for (int j = 0; j < 8; j++) acc[i][j] = 0.f;

    int lm = tid >> 1;               // node within tile this thread loads
    int lk = (tid & 1) * 8;          // k-offset within tile

    for (int kt = 0; kt < 8; kt++) {
        // W tile: rows kt*16..+16, 128 cols (2048 floats contiguous)
        const float4* Wg = (const float4*)(W + kt * 16 * 128);
        ((float4*)Ws)[tid]       = Wg[tid];
        ((float4*)Ws)[tid + 256] = Wg[tid + 256];
        // X tile transposed: thread loads 8 k-values of one node
        int node = bm + lm;
        float4 v0 = make_float4(0.f,0.f,0.f,0.f), v1 = v0;
        if (node < NN) {
            const float* xp = x + (size_t)node * 128 + kt * 16 + lk;
            v0 = *(const float4*)xp;
            v1 = *(const float4*)(xp + 4);
        }
        Xs[(lk + 0) * 128 + lm] = v0.x;
        Xs[(lk + 1) * 128 + lm] = v0.y;
        Xs[(lk + 2) * 128 + lm] = v0.z;
        Xs[(lk + 3) * 128 + lm] = v0.w;
        Xs[(lk + 4) * 128 + lm] = v1.x;
        Xs[(lk + 5) * 128 + lm] = v1.y;
        Xs[(lk + 6) * 128 + lm] = v1.z;
        Xs[(lk + 7) * 128 + lm] = v1.w;
        __syncthreads();
#pragma unroll
        for (int kk = 0; kk < 16; kk++) {
            float4 a0 = *(const float4*)&Xs[kk * 128 + ty * 8];
            float4 a1 = *(const float4*)&Xs[kk * 128 + ty * 8 + 4];
            float4 b0 = *(const float4*)&Ws[kk * 128 + tx * 8];
            float4 b1 = *(const float4*)&Ws[kk * 128 + tx * 8 + 4];
            float a[8] = {a0.x,a0.y,a0.z,a0.w,a1.x,a1.y,a1.z,a1.w};
            float b[8] = {b0.x,b0.y,b0.z,b0.w,b1.x,b1.y,b1.z,b1.w};
#pragma unroll
            for (int i = 0; i < 8; i++)
#pragma unroll
                for (int j = 0; j < 8; j++) acc[i][j] += a[i] * b[j];
        }
        __syncthreads();
    }
#pragma unroll
    for (int i = 0; i < 8; i++) {
        int node = bm + ty * 8 + i;
        if (node < NN) {
            float* op = g_h1 + (size_t)node * 128 + tx * 8;
            *(float4*)op       = make_float4(acc[i][0], acc[i][1], acc[i][2], acc[i][3]);
            *(float4*)(op + 4) = make_float4(acc[i][4], acc[i][5], acc[i][6], acc[i][7]);
        }
    }
}

// ---------------- attention scalars layer1 ----------------------------------
__global__ void k_al1(const float* __restrict__ a_src, const float* __restrict__ a_dst) {
    int i = blockIdx.x * blockDim.x + threadIdx.x;
    if (i >= NN * H) return;
    int n = i >> 2, h = i & 3;
    const float* hp = g_h1 + (size_t)n * 128 + h * 32;
    float s = 0.f, d = 0.f;
#pragma unroll
    for (int j = 0; j < 8; j++) {
        float4 v  = *(const float4*)(hp + j * 4);
        float4 as = *(const float4*)(a_src + h * 32 + j * 4);
        float4 ad = *(const float4*)(a_dst + h * 32 + j * 4);
        s += v.x * as.x + v.y * as.y + v.z * as.z + v.w * as.w;
        d += v.x * ad.x + v.y * ad.y + v.z * ad.z + v.w * ad.w;
    }
    g_als1[i] = s;
    g_ald1[i] = d;
}

// ---------------- layer1: logits + exp + denom (single pass, no max) ---------
__global__ void k_soft1() {
    int i = blockIdx.x * blockDim.x + threadIdx.x;
    if (i >= ETOT) return;
    int s = g_src[i], d = g_dst[i];
    float4 as = *(const float4*)(g_als1 + s * 4);
    float4 ad = *(const float4*)(g_ald1 + d * 4);
    float4 p;
    p.x = __expf(lrelu(as.x + ad.x));
    p.y = __expf(lrelu(as.y + ad.y));
    p.z = __expf(lrelu(as.z + ad.z));
    p.w = __expf(lrelu(as.w + ad.w));
    *(float4*)(g_e1 + (size_t)i * 4) = p;
    red_add_v4(&g_d1[d * 4], p);
}

// ---------------- invert denominators ----------------------------------------
__global__ void k_inv1() {
    int i = blockIdx.x * blockDim.x + threadIdx.x;
    if (i < NN * H) g_d1[i] = 1.f / fmaxf(g_d1[i], 1e-16f);
    if (i < NN)     g_d2[i] = g_d2[i];  // no-op lane reuse (kept trivial)
}

// ---------------- layer1 aggregate (warp per edge) ----------------------------
__global__ void k_agg1() {
    int gid = blockIdx.x * blockDim.x + threadIdx.x;
    int w = gid >> 5, lane = gid & 31;
    if (w >= ETOT) return;
    int s = g_src[w], d = g_dst[w];
    int head = lane >> 3;
    float alpha = g_e1[(size_t)w * 4 + head] * g_d1[d * 4 + head];
    float4 v = *(const float4*)(g_h1 + (size_t)s * 128 + lane * 4);
    v.x *= alpha; v.y *= alpha; v.z *= alpha; v.w *= alpha;
    red_add_v4(g_out1 + (size_t)d * 128 + lane * 4, v);
}

// ---------------- GEMM2 (ELU fused on load): h2 = elu(out1) @ W2 -------------
__global__ void k_gemm2(const float* __restrict__ W) {
    __shared__ float Ws[128 * 32];   // [k][c]
    __shared__ float Xs[64 * 128];   // [m][k]
    int tid = threadIdx.x;
    int tx = tid & 31;               // col
    int ty = tid >> 5;               // node group of 8
    int bm = blockIdx.x * 64;

    float4* Ws4 = (float4*)Ws;
    const float4* Wg = (const float4*)W;
#pragma unroll
    for (int r = 0; r < 4; r++) Ws4[tid + r * 256] = Wg[tid + r * 256];

    float4* Xs4 = (float4*)Xs;
#pragma unroll
    for (int r = 0; r < 8; r++) {
        int v = tid + r * 256;       // float4 index; 32 per row
        int m = v >> 5, kv = v & 31;
        int node = bm + m;
        float4 val = make_float4(0.f, 0.f, 0.f, 0.f);
        if (node < NN) {
            val = *(const float4*)(g_out1 + (size_t)node * 128 + kv * 4);
            val.x = val.x > 0.f ? val.x : __expf(val.x) - 1.f;
            val.y = val.y > 0.f ? val.y : __expf(val.y) - 1.f;
            val.z = val.z > 0.f ? val.z : __expf(val.z) - 1.f;
            val.w = val.w > 0.f ? val.w : __expf(val.w) - 1.f;
        }
        Xs4[v] = val;
    }
    __syncthreads();

    float acc[8];
#pragma unroll
    for (int i = 0; i < 8; i++) acc[i] = 0.f;
#pragma unroll 8
    for (int k = 0; k < 128; k++) {
        float w = Ws[k * 32 + tx];
#pragma unroll
        for (int i = 0; i < 8; i++) acc[i] += Xs[(ty * 8 + i) * 128 + k] * w;
    }
#pragma unroll
    for (int i = 0; i < 8; i++) {
        int node = bm + ty * 8 + i;
        if (node < NN) g_h2[(size_t)node * 32 + tx] = acc[i];
    }
}

// ---------------- attention scalars layer2 ----------------------------------
__global__ void k_al2(const float* __restrict__ a_src, const float* __restrict__ a_dst) {
    int n = blockIdx.x * blockDim.x + threadIdx.x;
    if (n >= NN) return;
    const float* hp = g_h2 + (size_t)n * 32;
    float s = 0.f, d = 0.f;
#pragma unroll
    for (int j = 0; j < 8; j++) {
        float4 v  = *(const float4*)(hp + j * 4);
        float4 as = *(const float4*)(a_src + j * 4);
        float4 ad = *(const float4*)(a_dst + j * 4);
        s += v.x * as.x + v.y * as.y + v.z * as.z + v.w * as.w;
        d += v.x * ad.x + v.y * ad.y + v.z * ad.z + v.w * ad.w;
    }
    g_als2[n] = s;
    g_ald2[n] = d;
}

// ---------------- layer2: logits + exp + denom --------------------------------
__global__ void k_soft2() {
    int i = blockIdx.x * blockDim.x + threadIdx.x;
    if (i >= ETOT) return;
    int s = g_src[i], d = g_dst[i];
    float p = __expf(lrelu(g_als2[s] + g_ald2[d]));
    g_e2[i] = p;
    atomicAdd(&g_d2[d], p);
}

__global__ void k_inv2() {
    int n = blockIdx.x * blockDim.x + threadIdx.x;
    if (n < NN) g_d2[n] = 1.f / fmaxf(g_d2[n], 1e-16f);
}

// ---------------- layer2 aggregate (8 threads per edge) -----------------------
__global__ void k_agg2(float* __restrict__ out) {
    int gid = blockIdx.x * blockDim.x + threadIdx.x;
    int e = gid >> 3, j = gid & 7;
    if (e >= ETOT) return;
    int s = g_src[e], d = g_dst[e];
    float alpha = g_e2[e] * g_d2[d];
    float4 v = *(const float4*)(g_h2 + (size_t)s * 32 + j * 4);
    v.x *= alpha; v.y *= alpha; v.z *= alpha; v.w *= alpha;
    red_add_v4(out + (size_t)d * 32 + j * 4, v);
}

// ---------------- launcher ---------------------------------------------------
extern "C" void kernel_launch(void* const* d_in, const int* in_sizes, int n_in,
                              void* d_out, int out_size) {
    const float* x      = (const float*)d_in[0];
    const float* W1     = (const float*)d_in[1];
    const float* a_src1 = (const float*)d_in[2];
    const float* a_dst1 = (const float*)d_in[3];
    const float* b1     = (const float*)d_in[4];
    const float* W2     = (const float*)d_in[5];
    const float* a_src2 = (const float*)d_in[6];
    const float* a_dst2 = (const float*)d_in[7];
    const float* b2     = (const float*)d_in[8];
    const void*  ei     = (const void*)d_in[9];
    float* out = (float*)d_out;

    k_detect<<<1, 256>>>((const int*)ei);
    k_decode<<<(ETOT + 255) / 256, 256>>>(ei);
    k_init  <<<(NN * F1 + 255) / 256, 256>>>(out, b1, b2);
    k_gemm1 <<<(NN + 127) / 128,      256>>>(x, W1);
    k_al1   <<<(NN * H + 255) / 256,  256>>>(a_src1, a_dst1);
    k_soft1 <<<(ETOT + 255) / 256,    256>>>();
    k_inv1  <<<(NN * H + 255) / 256,  256>>>();
    k_agg1  <<<(ETOT * 32 + 255) / 256, 256>>>();
    k_gemm2 <<<(NN + 63) / 64,        256>>>(W2);
    k_al2   <<<(NN + 255) / 256,      256>>>(a_src2, a_dst2);
    k_soft2 <<<(ETOT + 255) / 256,    256>>>();
    k_inv2  <<<(NN + 255) / 256,      256>>>();
    k_agg2  <<<(ETOT * 8 + 255) / 256, 256>>>(out);
}